// round 5
// baseline (speedup 1.0000x reference)
#include <cuda_runtime.h>
#include <cstdint>
#include <cstddef>

#define B 256
#define L 2048
#define H 128
#define V 32000
#define BL (B * L)
#define TOK 128   // tokens per encode block

typedef unsigned long long u64;

// Packed dual-FMA: d = a*b + c elementwise on float2 (sm_100+ f32x2 pipe).
__device__ __forceinline__ float2 ffma2(float2 a, float2 b, float2 c) {
    float2 d;
    asm("fma.rn.f32x2 %0, %1, %2, %3;"
        : "=l"(*(u64*)&d)
        : "l"(*(u64*)&a), "l"(*(u64*)&b), "l"(*(u64*)&c));
    return d;
}

// Scratch (no cudaMalloc allowed): device globals.
__device__ float g_h[(size_t)BL * H];   // 256 MB: encoded h_all [B,L,H]
__device__ float g_r[B * H];            // r = M_fin @ h_last
__device__ float g_rp[B * H];           // rp = r @ Wrp + brp

// ---------------------------------------------------------------------------
// Encode: h_all = LN(e + relu(e@W1+b1)@W2 + b2) * gamma + beta
// Block = 256 threads, 128 tokens. SMEM: e[128][128] (64KB) + h1[128][256] (128KB).
// All GEMM FMAs packed as f32x2 along output columns.
// ---------------------------------------------------------------------------
__global__ void __launch_bounds__(256, 1) encode_kernel(
    const int* __restrict__ seq, const float* __restrict__ embed,
    const float* __restrict__ W1, const float* __restrict__ b1,
    const float* __restrict__ W2, const float* __restrict__ b2,
    const float* __restrict__ gamma, const float* __restrict__ beta)
{
    extern __shared__ float sm[];
    float* e_sm  = sm;             // [TOK][H]
    float* h1_sm = sm + TOK * H;   // [TOK][2H]
    __shared__ int toks[TOK];

    const int t = threadIdx.x;
    const int tile0 = blockIdx.x * TOK;

    if (t < TOK) toks[t] = seq[tile0 + t];
    __syncthreads();

    // Gather embeddings: coalesced over the H dimension.
    #pragma unroll
    for (int i = 0; i < (TOK * H) / 256; i++) {
        int idx = i * 256 + t;
        int m = idx >> 7;
        int k = idx & (H - 1);
        e_sm[idx] = embed[(size_t)toks[m] * H + k];
    }
    __syncthreads();

    const int tx = t & 31;       // lane
    const int ty = t >> 5;       // warp 0..7
    const int m0 = ty * 16;      // 16 tokens per warp

    // ---------------- GEMM1: h1 = relu(e @ W1 + b1), N=256, K=128 ----------
    {
        const int n0 = tx * 8;
        float2 acc[16][4];   // col-pairs (n0+2j, n0+2j+1)
        #pragma unroll
        for (int i = 0; i < 16; i++)
            #pragma unroll
            for (int j = 0; j < 4; j++) acc[i][j] = make_float2(0.f, 0.f);

        #pragma unroll 2
        for (int k = 0; k < H; k++) {
            float4 w0 = *(const float4*)(W1 + (size_t)k * 256 + n0);
            float4 w1 = *(const float4*)(W1 + (size_t)k * 256 + n0 + 4);
            const float2* wp0 = reinterpret_cast<const float2*>(&w0);
            const float2* wp1 = reinterpret_cast<const float2*>(&w1);
            #pragma unroll
            for (int i = 0; i < 16; i++) {
                float ev = e_sm[(m0 + i) * H + k];   // broadcast LDS
                float2 ev2 = make_float2(ev, ev);
                acc[i][0] = ffma2(ev2, wp0[0], acc[i][0]);
                acc[i][1] = ffma2(ev2, wp0[1], acc[i][1]);
                acc[i][2] = ffma2(ev2, wp1[0], acc[i][2]);
                acc[i][3] = ffma2(ev2, wp1[1], acc[i][3]);
            }
        }
        float4 bb0 = *(const float4*)(b1 + n0);
        float4 bb1 = *(const float4*)(b1 + n0 + 4);
        #pragma unroll
        for (int i = 0; i < 16; i++) {
            float4 r0, r1;
            r0.x = fmaxf(acc[i][0].x + bb0.x, 0.f);
            r0.y = fmaxf(acc[i][0].y + bb0.y, 0.f);
            r0.z = fmaxf(acc[i][1].x + bb0.z, 0.f);
            r0.w = fmaxf(acc[i][1].y + bb0.w, 0.f);
            r1.x = fmaxf(acc[i][2].x + bb1.x, 0.f);
            r1.y = fmaxf(acc[i][2].y + bb1.y, 0.f);
            r1.z = fmaxf(acc[i][3].x + bb1.z, 0.f);
            r1.w = fmaxf(acc[i][3].y + bb1.w, 0.f);
            *(float4*)(h1_sm + (m0 + i) * 256 + n0)     = r0;
            *(float4*)(h1_sm + (m0 + i) * 256 + n0 + 4) = r1;
        }
    }
    __syncthreads();

    // ---------------- GEMM2: ff = h1 @ W2 + b2, N=128, K=256 ---------------
    const int c0 = tx * 4;
    float2 acc2[16][2];
    #pragma unroll
    for (int i = 0; i < 16; i++) {
        acc2[i][0] = make_float2(0.f, 0.f);
        acc2[i][1] = make_float2(0.f, 0.f);
    }

    #pragma unroll 2
    for (int k = 0; k < 2 * H; k++) {
        float4 w = *(const float4*)(W2 + (size_t)k * H + c0);
        const float2* wp = reinterpret_cast<const float2*>(&w);
        #pragma unroll
        for (int i = 0; i < 16; i++) {
            float hv = h1_sm[(m0 + i) * 256 + k];   // broadcast LDS
            float2 h2 = make_float2(hv, hv);
            acc2[i][0] = ffma2(h2, wp[0], acc2[i][0]);
            acc2[i][1] = ffma2(h2, wp[1], acc2[i][1]);
        }
    }

    // ---------------- residual + LayerNorm + write --------------------------
    const float4 gv  = *(const float4*)(gamma + c0);
    const float4 bv  = *(const float4*)(beta + c0);
    const float4 b2v = *(const float4*)(b2 + c0);
    #pragma unroll
    for (int i = 0; i < 16; i++) {
        int m = m0 + i;
        const float4 ev = *(const float4*)(e_sm + m * H + c0);
        float y0 = acc2[i][0].x + b2v.x + ev.x;
        float y1 = acc2[i][0].y + b2v.y + ev.y;
        float y2 = acc2[i][1].x + b2v.z + ev.z;
        float y3 = acc2[i][1].y + b2v.w + ev.w;
        float s = (y0 + y1) + (y2 + y3);
        float q = y0 * y0 + y1 * y1 + y2 * y2 + y3 * y3;
        #pragma unroll
        for (int o = 16; o; o >>= 1) {
            s += __shfl_xor_sync(0xffffffffu, s, o);
            q += __shfl_xor_sync(0xffffffffu, q, o);
        }
        float mu  = s * (1.0f / H);
        float var = q * (1.0f / H) - mu * mu;
        float inv = rsqrtf(var + 1e-5f);
        float4 o4;
        o4.x = (y0 - mu) * inv * gv.x + bv.x;
        o4.y = (y1 - mu) * inv * gv.y + bv.y;
        o4.z = (y2 - mu) * inv * gv.z + bv.z;
        o4.w = (y3 - mu) * inv * gv.w + bv.w;
        *(float4*)(g_h + (size_t)(tile0 + m) * H + c0) = o4;
    }
}

// ---------------------------------------------------------------------------
// Scan: one CTA per batch. Thread i owns M row i as float2[64] in registers.
// 2047 sequential delta-rule steps, all FMAs packed f32x2.
// ---------------------------------------------------------------------------
__global__ void __launch_bounds__(128, 2) scan_kernel()
{
    const int b = blockIdx.x;
    const int tid = threadIdx.x;
    const int lane = tid & 31;
    const int wid = tid >> 5;

    __shared__ float ks[2][H];
    __shared__ float red_kk[4];
    __shared__ float red_ee[4];

    float2 Mr[64];
    #pragma unroll
    for (int q = 0; q < 64; q++) Mr[q] = make_float2(0.f, 0.f);

    const float* hb = g_h + (size_t)b * L * H;
    float kv_next = hb[tid];   // k_0

    for (int t = 0; t < L - 1; t++) {
        const int buf = t & 1;
        const float kv = kv_next;
        ks[buf][tid] = kv;

        // kk = ||k||^2 (block reduce)
        float p = kv * kv;
        #pragma unroll
        for (int o = 16; o; o >>= 1) p += __shfl_xor_sync(0xffffffffu, p, o);
        if (lane == 0) red_kk[wid] = p;
        __syncthreads();                                   // BAR1

        kv_next = hb[(size_t)(t + 1) * H + tid];           // prefetch (t=2046 -> h_last)
        const float kk = (red_kk[0] + red_kk[1]) + (red_kk[2] + red_kk[3]);

        // vp_i = M_i . k   (4 packed accumulator chains)
        const float4* k4 = (const float4*)ks[buf];
        float2 a0 = make_float2(0.f, 0.f), a1 = a0, a2 = a0, a3 = a0;
        #pragma unroll
        for (int q = 0; q < 32; q += 2) {
            float4 ka = k4[q];
            float4 kb = k4[q + 1];
            const float2* kap = reinterpret_cast<const float2*>(&ka);
            const float2* kbp = reinterpret_cast<const float2*>(&kb);
            a0 = ffma2(Mr[2 * q + 0], kap[0], a0);
            a1 = ffma2(Mr[2 * q + 1], kap[1], a1);
            a2 = ffma2(Mr[2 * q + 2], kbp[0], a2);
            a3 = ffma2(Mr[2 * q + 3], kbp[1], a3);
        }
        const float vp = ((a0.x + a0.y) + (a1.x + a1.y))
                       + ((a2.x + a2.y) + (a3.x + a3.y));
        const float err = kv - vp / (kk + 1e-6f);

        // ee = ||err||^2 (block reduce)
        float pe = err * err;
        #pragma unroll
        for (int o = 16; o; o >>= 1) pe += __shfl_xor_sync(0xffffffffu, pe, o);
        if (lane == 0) red_ee[wid] = pe;
        __syncthreads();                                   // BAR2
        const float ee = (red_ee[0] + red_ee[1]) + (red_ee[2] + red_ee[3]);

        // gate = ||err|| > 0.4*||v||   (v = k  =>  compare squares)
        if (ee > 0.16f * kk) {                              // uniform branch
            const float2 e2 = make_float2(err, err);
            #pragma unroll
            for (int q = 0; q < 32; q++) {
                float4 kq = k4[q];
                const float2* kp = reinterpret_cast<const float2*>(&kq);
                Mr[2 * q + 0] = ffma2(e2, kp[0], Mr[2 * q + 0]);
                Mr[2 * q + 1] = ffma2(e2, kp[1], Mr[2 * q + 1]);
            }
        }
    }

    // Epilogue: r_i = M_i . h_last  (kv_next holds h_last[tid])
    ks[1][tid] = kv_next;
    __syncthreads();
    const float4* k4 = (const float4*)ks[1];
    float2 a0 = make_float2(0.f, 0.f), a1 = a0, a2 = a0, a3 = a0;
    #pragma unroll
    for (int q = 0; q < 32; q += 2) {
        float4 ka = k4[q];
        float4 kb = k4[q + 1];
        const float2* kap = reinterpret_cast<const float2*>(&ka);
        const float2* kbp = reinterpret_cast<const float2*>(&kb);
        a0 = ffma2(Mr[2 * q + 0], kap[0], a0);
        a1 = ffma2(Mr[2 * q + 1], kap[1], a1);
        a2 = ffma2(Mr[2 * q + 2], kbp[0], a2);
        a3 = ffma2(Mr[2 * q + 3], kbp[1], a3);
    }
    g_r[b * H + tid] = ((a0.x + a0.y) + (a1.x + a1.y))
                     + ((a2.x + a2.y) + (a3.x + a3.y));
}

// ---------------------------------------------------------------------------
// rp = r @ Wrp + brp   (tiny: 256 blocks x 128 threads)
// ---------------------------------------------------------------------------
__global__ void rp_kernel(const float* __restrict__ Wrp, const float* __restrict__ brp)
{
    const int b = blockIdx.x;
    const int i = threadIdx.x;
    __shared__ float rb[H];
    rb[i] = g_r[b * H + i];
    __syncthreads();
    float acc = brp[i];
    #pragma unroll 8
    for (int j = 0; j < H; j++) acc += rb[j] * Wrp[j * H + i];
    g_rp[b * H + i] = acc;
}

// ---------------------------------------------------------------------------
// out = rp @ Wout + bout.  Block: 256 thr, tile 64 batches x 128 vocab.
// ---------------------------------------------------------------------------
__global__ void __launch_bounds__(256) out_kernel(
    const float* __restrict__ Wout, const float* __restrict__ bout,
    float* __restrict__ out)
{
    __shared__ float rp_sm[64 * H];   // 32 KB
    const int t = threadIdx.x;
    const int v0 = blockIdx.x * 128;
    const int b0 = blockIdx.y * 64;

    #pragma unroll
    for (int i = 0; i < 32; i++) {
        int idx = i * 256 + t;
        rp_sm[idx] = g_rp[b0 * H + idx];
    }
    __syncthreads();

    const int tx = t & 31;
    const int ty = t >> 5;
    const int m0 = ty * 8;
    const int n  = v0 + tx * 4;

    float2 acc[8][2];
    #pragma unroll
    for (int i = 0; i < 8; i++) {
        acc[i][0] = make_float2(0.f, 0.f);
        acc[i][1] = make_float2(0.f, 0.f);
    }

    #pragma unroll 2
    for (int k = 0; k < H; k++) {
        float4 w = *(const float4*)(Wout + (size_t)k * V + n);
        const float2* wp = reinterpret_cast<const float2*>(&w);
        #pragma unroll
        for (int i = 0; i < 8; i++) {
            float hv = rp_sm[(m0 + i) * H + k];   // broadcast LDS
            float2 h2 = make_float2(hv, hv);
            acc[i][0] = ffma2(h2, wp[0], acc[i][0]);
            acc[i][1] = ffma2(h2, wp[1], acc[i][1]);
        }
    }
    const float4 bo = *(const float4*)(bout + n);
    #pragma unroll
    for (int i = 0; i < 8; i++) {
        float4 o;
        o.x = acc[i][0].x + bo.x; o.y = acc[i][0].y + bo.y;
        o.z = acc[i][1].x + bo.z; o.w = acc[i][1].y + bo.w;
        *(float4*)(out + (size_t)(b0 + m0 + i) * V + n) = o;
    }
}

// ---------------------------------------------------------------------------
extern "C" void kernel_launch(void* const* d_in, const int* in_sizes, int n_in,
                              void* d_out, int out_size)
{
    const int*   seq   = (const int*)  d_in[0];
    const float* embed = (const float*)d_in[1];
    const float* W1    = (const float*)d_in[2];
    const float* b1    = (const float*)d_in[3];
    const float* W2    = (const float*)d_in[4];
    const float* b2    = (const float*)d_in[5];
    const float* gamma = (const float*)d_in[6];
    const float* beta  = (const float*)d_in[7];
    const float* Wrp   = (const float*)d_in[8];
    const float* brp   = (const float*)d_in[9];
    const float* Wout  = (const float*)d_in[10];
    const float* bout  = (const float*)d_in[11];
    float* out = (float*)d_out;

    const size_t enc_smem = (size_t)(TOK * H + TOK * 2 * H) * sizeof(float); // 196608
    cudaFuncSetAttribute(encode_kernel,
                         cudaFuncAttributeMaxDynamicSharedMemorySize,
                         (int)enc_smem);

    encode_kernel<<<BL / TOK, 256, enc_smem>>>(seq, embed, W1, b1, W2, b2, gamma, beta);
    scan_kernel<<<B, 128>>>();
    rp_kernel<<<B, H>>>(Wrp, brp);
    dim3 og(V / 128, B / 64);
    out_kernel<<<og, 256>>>(Wout, bout, out);
}

// round 9
// speedup vs baseline: 1.3098x; 1.3098x over previous
#include <cuda_runtime.h>
#include <cuda_bf16.h>
#include <cstdint>
#include <cstddef>

#define B 256
#define L 2048
#define H 128
#define V 32000
#define BL (B * L)
#define TOK 128

typedef unsigned long long u64;
typedef uint32_t u32;

// ---------------------------------------------------------------------------
// helpers
// ---------------------------------------------------------------------------
__device__ __forceinline__ u32 smem_u32(const void* p) {
    return (u32)__cvta_generic_to_shared(p);
}

__device__ __forceinline__ void ldsm_x4(u32* r, u32 addr) {
    asm volatile("ldmatrix.sync.aligned.m8n8.x4.shared.b16 {%0,%1,%2,%3}, [%4];"
                 : "=r"(r[0]), "=r"(r[1]), "=r"(r[2]), "=r"(r[3]) : "r"(addr));
}

__device__ __forceinline__ void mma16816(float* d, const u32* a, u32 b0, u32 b1) {
    asm volatile(
        "mma.sync.aligned.m16n8k16.row.col.f32.bf16.bf16.f32 "
        "{%0,%1,%2,%3}, {%4,%5,%6,%7}, {%8,%9}, {%0,%1,%2,%3};"
        : "+f"(d[0]), "+f"(d[1]), "+f"(d[2]), "+f"(d[3])
        : "r"(a[0]), "r"(a[1]), "r"(a[2]), "r"(a[3]), "r"(b0), "r"(b1));
}

__device__ __forceinline__ void cp16(u32 dst, const void* src) {
    asm volatile("cp.async.cg.shared.global [%0], [%1], 16;" :: "r"(dst), "l"(src));
}

// Packed dual-FMA (scan/out kernels).
__device__ __forceinline__ float2 ffma2(float2 a, float2 b, float2 c) {
    float2 d;
    asm("fma.rn.f32x2 %0, %1, %2, %3;"
        : "=l"(*(u64*)&d)
        : "l"(*(u64*)&a), "l"(*(u64*)&b), "l"(*(u64*)&c));
    return d;
}

// 3-way bf16 split: x = a0+a1+a2 + O(2^-27 * x)
__device__ __forceinline__ void split3(float x, __nv_bfloat16* a) {
    a[0] = __float2bfloat16(x);
    float r = x - __bfloat162float(a[0]);
    a[1] = __float2bfloat16(r);  r -= __bfloat162float(a[1]);
    a[2] = __float2bfloat16(r);
}
__device__ __forceinline__ u32 pack_bf2(__nv_bfloat16 lo, __nv_bfloat16 hi) {
    __nv_bfloat162 p;
    p.x = lo; p.y = hi;
    return *(u32*)&p;
}

// XOR chunk swizzles: conflict-free ldmatrix on natural row strides.
__device__ __forceinline__ u32 swz256(int row, int kb) {
    return (u32)(row * 256 + ((((kb >> 4) ^ (row & 7)) << 4) | (kb & 15)));
}
__device__ __forceinline__ u32 swz128(int row, int kb) {
    return (u32)(row * 128 + ((((kb >> 4) ^ (row & 7)) << 4) | (kb & 15)));
}

// ---------------------------------------------------------------------------
// Scratch device globals.
// ---------------------------------------------------------------------------
__device__ float g_h[(size_t)BL * H];
__device__ float g_r[B * H];
__device__ float g_rp[B * H];
// Pre-split, pre-swizzled weight part-tiles (3 parts):
// g_W1s: [c=4][p=3][16384]  tile = 64 n-rows x 128 k bf16, swz256 rows
// g_W2s: [c=4][p=3][16384]  tile = 128 n-rows x 64 k bf16, swz128 rows
__device__ unsigned char g_W1s[4 * 3 * 16384];
__device__ unsigned char g_W2s[4 * 3 * 16384];

// ---------------------------------------------------------------------------
// Prep: split3 + transpose + swizzle the weights.
// ---------------------------------------------------------------------------
__global__ void __launch_bounds__(256) prep_kernel(
    const float* __restrict__ W1, const float* __restrict__ W2)
{
    int idx = blockIdx.x * 256 + threadIdx.x;   // 65536 total
    __nv_bfloat16 pp[3];
    if (idx < H * 2 * H) {                      // W1: [k=128][n=256]
        int k = idx >> 8;
        int n = idx & 255;
        split3(W1[idx], pp);
        int c = n >> 6, nl = n & 63;
        u32 off = swz256(nl, 2 * k);
        unsigned char* base = g_W1s + (size_t)c * 49152 + off;
        #pragma unroll
        for (int p = 0; p < 3; p++)
            *(__nv_bfloat16*)(base + p * 16384) = pp[p];
    } else {                                    // W2: [k2=256][n=128]
        int j  = idx - H * 2 * H;
        int k2 = j >> 7;
        int n  = j & 127;
        split3(W2[j], pp);
        int c = k2 >> 6, kl = k2 & 63;
        u32 off = swz128(n, 2 * kl);
        unsigned char* base = g_W2s + (size_t)c * 49152 + off;
        #pragma unroll
        for (int p = 0; p < 3; p++)
            *(__nv_bfloat16*)(base + p * 16384) = pp[p];
    }
}

// Stage schedule: s = c*6 + g*3 + jj, W part j = 2-jj (smallest products first).
__device__ __forceinline__ const unsigned char* stage_src(int s) {
    int c = s / 6, g = (s / 3) % 2, jj = s % 3;
    int j = 2 - jj;
    return (g ? g_W2s : g_W1s) + (size_t)c * 49152 + (size_t)j * 16384;
}

// ---------------------------------------------------------------------------
// Encode via bf16 mma.sync, 3-way split (6 products), re-rolled accumulation
// order: W parts streamed j=2,1,0; A parts i descending; k16 descending.
// 256 threads, 128 tokens per CTA, grid 4096, 1 CTA/SM.
// SMEM (182784 B): E 3x32768 @0 | A2 3x16384 @98304 | W 2x16384 @147456
//                  consts @180224 (b1 256f, b2/g/b 128f each)
// ---------------------------------------------------------------------------
#define EO       0
#define EPART    32768
#define A2O      98304
#define A2PART   16384
#define WO       147456
#define CO       180224
#define ENC_SMEM 182784

__global__ void __launch_bounds__(256, 1) encode_mma_kernel(
    const int* __restrict__ seq, const float* __restrict__ embed,
    const float* __restrict__ b1, const float* __restrict__ b2,
    const float* __restrict__ gamma, const float* __restrict__ beta)
{
    extern __shared__ char smc[];
    const u32 sb = smem_u32(smc);
    float* b1s = (float*)(smc + CO);
    float* b2s = b1s + 256;
    float* gs  = b2s + 128;
    float* bs  = gs + 128;

    const int t    = threadIdx.x;
    const int lane = t & 31;
    const int w    = t >> 5;
    const int tile0 = blockIdx.x * TOK;

    // Kick off first weight-part load immediately (overlaps E gather).
    {
        const unsigned char* src = stage_src(0) + t * 64;
        u32 dst = sb + WO + t * 64;
        cp16(dst, src); cp16(dst + 16, src + 16);
        cp16(dst + 32, src + 32); cp16(dst + 48, src + 48);
        asm volatile("cp.async.commit_group;");
    }

    b1s[t] = b1[t];
    if (t < 128) { b2s[t] = b2[t]; gs[t] = gamma[t]; bs[t] = beta[t]; }

    // ---- gather + split3 E: two threads per token ----
    {
        int row = t >> 1, kh = t & 1;
        int tok = seq[tile0 + row];
        const float4* er = (const float4*)(embed + (size_t)tok * H) + kh * 16;
        #pragma unroll 4
        for (int i = 0; i < 16; i++) {
            float4 v = er[i];
            int col0 = kh * 64 + 4 * i;
            u32 offA = swz256(row, 2 * col0);
            __nv_bfloat16 px[3], py[3];
            split3(v.x, px); split3(v.y, py);
            #pragma unroll
            for (int p = 0; p < 3; p++)
                *(u32*)(smc + EO + p * EPART + offA) = pack_bf2(px[p], py[p]);
            split3(v.z, px); split3(v.w, py);
            #pragma unroll
            for (int p = 0; p < 3; p++)
                *(u32*)(smc + EO + p * EPART + offA + 4) = pack_bf2(px[p], py[p]);
        }
    }

    const int m0   = (w >> 1) * 32;
    const int n0g1 = (w & 1) * 32;
    const int n0g2 = (w & 1) * 64;
    const int lg   = lane >> 3;
    const int rsel = (lane & 7) + ((lg & 1) << 3);
    const int kbs  = (lg >> 1) << 4;
    const int frow = lane >> 2;
    const int fcol = 2 * (lane & 3);

    float c1[2][4][4];
    float c2[2][8][4];
    #pragma unroll
    for (int mt = 0; mt < 2; mt++)
        #pragma unroll
        for (int nt = 0; nt < 8; nt++)
            #pragma unroll
            for (int jj = 0; jj < 4; jj++) c2[mt][nt][jj] = 0.f;

    // ---- 24 stages: chunk c x {GEMM1 parts j=2,1,0 ; GEMM2 parts j=2,1,0} ----
    for (int s = 0; s < 24; s++) {
        const int jj  = s % 3;       // stream index
        const int j   = 2 - jj;      // W part (2 first, 0 = dominant last)
        const int g   = (s / 3) % 2;
        const int buf = s & 1;

        __syncthreads();   // previous stage's compute done -> other buf reusable
        if (s < 23) {
            const unsigned char* src = stage_src(s + 1) + t * 64;
            u32 dst = sb + WO + ((s + 1) & 1) * 16384 + t * 64;
            cp16(dst, src); cp16(dst + 16, src + 16);
            cp16(dst + 32, src + 32); cp16(dst + 48, src + 48);
            asm volatile("cp.async.commit_group;");
            asm volatile("cp.async.wait_group 1;");
        } else {
            asm volatile("cp.async.wait_group 0;");
        }
        __syncthreads();   // stage-s weight part visible to all

        const u32 Bb = sb + WO + buf * 16384;

        if (g == 0) {
            // ---------------- GEMM1: C1 += E_i @ W1c_j^T ----------------
            if (jj == 0) {
                #pragma unroll
                for (int mt = 0; mt < 2; mt++)
                    #pragma unroll
                    for (int nt = 0; nt < 4; nt++)
                        #pragma unroll
                        for (int q = 0; q < 4; q++) c1[mt][nt][q] = 0.f;
            }
            for (int i = 2 - j; i >= 0; i--) {          // small first, a0 last
                const u32 Ab = sb + EO + i * EPART;
                #pragma unroll
                for (int k16 = 7; k16 >= 0; k16--) {    // reversed k-chunks
                    const int kb = k16 * 32 + kbs;
                    u32 a[2][4], q[2][4];
                    ldsm_x4(a[0], Ab + swz256(m0 + rsel, kb));
                    ldsm_x4(a[1], Ab + swz256(m0 + 16 + rsel, kb));
                    ldsm_x4(q[0], Bb + swz256(n0g1 + rsel, kb));
                    ldsm_x4(q[1], Bb + swz256(n0g1 + 16 + rsel, kb));
                    #pragma unroll
                    for (int mt = 0; mt < 2; mt++)
                        #pragma unroll
                        for (int nt = 0; nt < 4; nt++)
                            mma16816(c1[mt][nt], a[mt],
                                     q[nt >> 1][nt & 1], q[nt >> 1][2 + (nt & 1)]);
                }
            }
            if (jj == 2) {
                // ---- bias + relu + split3 -> A2 parts ----
                const int c = s / 6;
                #pragma unroll
                for (int mt = 0; mt < 2; mt++) {
                    #pragma unroll
                    for (int nt = 0; nt < 4; nt++) {
                        int col = n0g1 + nt * 8 + fcol;
                        float bb0 = b1s[c * 64 + col];
                        float bb1 = b1s[c * 64 + col + 1];
                        #pragma unroll
                        for (int half = 0; half < 2; half++) {
                            int row = m0 + mt * 16 + frow + half * 8;
                            float h0 = fmaxf(c1[mt][nt][2 * half + 0] + bb0, 0.f);
                            float h1 = fmaxf(c1[mt][nt][2 * half + 1] + bb1, 0.f);
                            __nv_bfloat16 px[3], py[3];
                            split3(h0, px); split3(h1, py);
                            u32 off = swz128(row, 2 * col);
                            #pragma unroll
                            for (int p = 0; p < 3; p++)
                                *(u32*)(smc + A2O + p * A2PART + off) =
                                    pack_bf2(px[p], py[p]);
                        }
                    }
                }
            }
        } else {
            // ---------------- GEMM2: C2 += A2_i @ W2c_j^T ----------------
            for (int i = 2 - j; i >= 0; i--) {
                const u32 Ab = sb + A2O + i * A2PART;
                #pragma unroll
                for (int k16 = 3; k16 >= 0; k16--) {
                    const int kb = k16 * 32 + kbs;
                    u32 a[2][4], q[4][4];
                    ldsm_x4(a[0], Ab + swz128(m0 + rsel, kb));
                    ldsm_x4(a[1], Ab + swz128(m0 + 16 + rsel, kb));
                    #pragma unroll
                    for (int nt2 = 0; nt2 < 4; nt2++)
                        ldsm_x4(q[nt2], Bb + swz128(n0g2 + nt2 * 16 + rsel, kb));
                    #pragma unroll
                    for (int mt = 0; mt < 2; mt++)
                        #pragma unroll
                        for (int nt = 0; nt < 8; nt++)
                            mma16816(c2[mt][nt], a[mt],
                                     q[nt >> 1][nt & 1], q[nt >> 1][2 + (nt & 1)]);
                }
            }
        }
    }

    // ---- epilogue: y = ff + b2 + e (e from 3 SMEM parts) ----
    #pragma unroll
    for (int mt = 0; mt < 2; mt++) {
        #pragma unroll
        for (int nt = 0; nt < 8; nt++) {
            int col = n0g2 + nt * 8 + fcol;
            float bb0 = b2s[col], bb1 = b2s[col + 1];
            #pragma unroll
            for (int half = 0; half < 2; half++) {
                int row = m0 + mt * 16 + frow + half * 8;
                u32 off = swz256(row, 2 * col);
                float e0 = 0.f, e1 = 0.f;
                #pragma unroll
                for (int p = 2; p >= 0; p--) {
                    u32 ev = *(u32*)(smc + EO + p * EPART + off);
                    __nv_bfloat162 eb = *(__nv_bfloat162*)&ev;
                    e0 += __bfloat162float(eb.x);
                    e1 += __bfloat162float(eb.y);
                }
                c2[mt][nt][2 * half + 0] += bb0 + e0;
                c2[mt][nt][2 * half + 1] += bb1 + e1;
            }
        }
    }
    __syncthreads();   // all E reads done before overwrite

    // ---- y -> ySM (stride 132 floats, reuses E region), LN, write g_h ----
    float* ySM = (float*)(smc + EO);
    float* muS = (float*)(smc + A2O);
    float* ivS = muS + 128;
    #pragma unroll
    for (int mt = 0; mt < 2; mt++) {
        #pragma unroll
        for (int nt = 0; nt < 8; nt++) {
            int col = n0g2 + nt * 8 + fcol;
            #pragma unroll
            for (int half = 0; half < 2; half++) {
                int row = m0 + mt * 16 + frow + half * 8;
                *(float2*)(ySM + row * 132 + col) =
                    make_float2(c2[mt][nt][2 * half + 0], c2[mt][nt][2 * half + 1]);
            }
        }
    }
    __syncthreads();

    if (t < 128) {
        const float4* yr = (const float4*)(ySM + t * 132);
        float s = 0.f, q = 0.f;
        #pragma unroll 8
        for (int jj = 0; jj < 32; jj++) {
            float4 y = yr[jj];
            s += (y.x + y.y) + (y.z + y.w);
            q += y.x * y.x + y.y * y.y + y.z * y.z + y.w * y.w;
        }
        float mu  = s * (1.0f / H);
        float var = q * (1.0f / H) - mu * mu;
        muS[t] = mu;
        ivS[t] = rsqrtf(var + 1e-5f);
    }
    __syncthreads();

    #pragma unroll
    for (int i = t; i < 128 * 32; i += 256) {
        int row = i >> 5, jj = i & 31;
        float4 y = ((const float4*)(ySM + row * 132))[jj];
        float mu = muS[row], iv = ivS[row];
        float4 g4 = ((const float4*)gs)[jj];
        float4 b4 = ((const float4*)bs)[jj];
        float4 o4;
        o4.x = (y.x - mu) * iv * g4.x + b4.x;
        o4.y = (y.y - mu) * iv * g4.y + b4.y;
        o4.z = (y.z - mu) * iv * g4.z + b4.z;
        o4.w = (y.w - mu) * iv * g4.w + b4.w;
        ((float4*)(g_h + (size_t)(tile0 + row) * H))[jj] = o4;
    }
}

// ---------------------------------------------------------------------------
// Scan: one CTA per batch (unchanged from R5).
// ---------------------------------------------------------------------------
__global__ void __launch_bounds__(128, 2) scan_kernel()
{
    const int b = blockIdx.x;
    const int tid = threadIdx.x;
    const int lane = tid & 31;
    const int wid = tid >> 5;

    __shared__ float ks[2][H];
    __shared__ float red_kk[4];
    __shared__ float red_ee[4];

    float2 Mr[64];
    #pragma unroll
    for (int q = 0; q < 64; q++) Mr[q] = make_float2(0.f, 0.f);

    const float* hb = g_h + (size_t)b * L * H;
    float kv_next = hb[tid];

    for (int t = 0; t < L - 1; t++) {
        const int buf = t & 1;
        const float kv = kv_next;
        ks[buf][tid] = kv;

        float p = kv * kv;
        #pragma unroll
        for (int o = 16; o; o >>= 1) p += __shfl_xor_sync(0xffffffffu, p, o);
        if (lane == 0) red_kk[wid] = p;
        __syncthreads();

        kv_next = hb[(size_t)(t + 1) * H + tid];
        const float kk = (red_kk[0] + red_kk[1]) + (red_kk[2] + red_kk[3]);

        const float4* k4 = (const float4*)ks[buf];
        float2 a0 = make_float2(0.f, 0.f), a1 = a0, a2 = a0, a3 = a0;
        #pragma unroll
        for (int q = 0; q < 32; q += 2) {
            float4 ka = k4[q];
            float4 kb = k4[q + 1];
            const float2* kap = reinterpret_cast<const float2*>(&ka);
            const float2* kbp = reinterpret_cast<const float2*>(&kb);
            a0 = ffma2(Mr[2 * q + 0], kap[0], a0);
            a1 = ffma2(Mr[2 * q + 1], kap[1], a1);
            a2 = ffma2(Mr[2 * q + 2], kbp[0], a2);
            a3 = ffma2(Mr[2 * q + 3], kbp[1], a3);
        }
        const float vp = ((a0.x + a0.y) + (a1.x + a1.y))
                       + ((a2.x + a2.y) + (a3.x + a3.y));
        const float err = kv - vp / (kk + 1e-6f);

        float pe = err * err;
        #pragma unroll
        for (int o = 16; o; o >>= 1) pe += __shfl_xor_sync(0xffffffffu, pe, o);
        if (lane == 0) red_ee[wid] = pe;
        __syncthreads();
        const float ee = (red_ee[0] + red_ee[1]) + (red_ee[2] + red_ee[3]);

        if (ee > 0.16f * kk) {
            const float2 e2 = make_float2(err, err);
            #pragma unroll
            for (int q = 0; q < 32; q++) {
                float4 kq = k4[q];
                const float2* kp = reinterpret_cast<const float2*>(&kq);
                Mr[2 * q + 0] = ffma2(e2, kp[0], Mr[2 * q + 0]);
                Mr[2 * q + 1] = ffma2(e2, kp[1], Mr[2 * q + 1]);
            }
        }
    }

    ks[1][tid] = kv_next;
    __syncthreads();
    const float4* k4 = (const float4*)ks[1];
    float2 a0 = make_float2(0.f, 0.f), a1 = a0, a2 = a0, a3 = a0;
    #pragma unroll
    for (int q = 0; q < 32; q += 2) {
        float4 ka = k4[q];
        float4 kb = k4[q + 1];
        const float2* kap = reinterpret_cast<const float2*>(&ka);
        const float2* kbp = reinterpret_cast<const float2*>(&kb);
        a0 = ffma2(Mr[2 * q + 0], kap[0], a0);
        a1 = ffma2(Mr[2 * q + 1], kap[1], a1);
        a2 = ffma2(Mr[2 * q + 2], kbp[0], a2);
        a3 = ffma2(Mr[2 * q + 3], kbp[1], a3);
    }
    g_r[b * H + tid] = ((a0.x + a0.y) + (a1.x + a1.y))
                     + ((a2.x + a2.y) + (a3.x + a3.y));
}

// ---------------------------------------------------------------------------
__global__ void rp_kernel(const float* __restrict__ Wrp, const float* __restrict__ brp)
{
    const int b = blockIdx.x;
    const int i = threadIdx.x;
    __shared__ float rb[H];
    rb[i] = g_r[b * H + i];
    __syncthreads();
    float acc = brp[i];
    #pragma unroll 8
    for (int j = 0; j < H; j++) acc += rb[j] * Wrp[j * H + i];
    g_rp[b * H + i] = acc;
}

// ---------------------------------------------------------------------------
__global__ void __launch_bounds__(256) out_kernel(
    const float* __restrict__ Wout, const float* __restrict__ bout,
    float* __restrict__ out)
{
    __shared__ float rp_sm[64 * H];
    const int t = threadIdx.x;
    const int v0 = blockIdx.x * 128;
    const int b0 = blockIdx.y * 64;

    #pragma unroll
    for (int i = 0; i < 32; i++) {
        int idx = i * 256 + t;
        rp_sm[idx] = g_rp[b0 * H + idx];
    }
    __syncthreads();

    const int tx = t & 31;
    const int ty = t >> 5;
    const int m0 = ty * 8;
    const int n  = v0 + tx * 4;

    float2 acc[8][2];
    #pragma unroll
    for (int i = 0; i < 8; i++) {
        acc[i][0] = make_float2(0.f, 0.f);
        acc[i][1] = make_float2(0.f, 0.f);
    }

    #pragma unroll 2
    for (int k = 0; k < H; k++) {
        float4 wv = *(const float4*)(Wout + (size_t)k * V + n);
        const float2* wp = reinterpret_cast<const float2*>(&wv);
        #pragma unroll
        for (int i = 0; i < 8; i++) {
            float hv = rp_sm[(m0 + i) * H + k];
            float2 h2 = make_float2(hv, hv);
            acc[i][0] = ffma2(h2, wp[0], acc[i][0]);
            acc[i][1] = ffma2(h2, wp[1], acc[i][1]);
        }
    }
    const float4 bo = *(const float4*)(bout + n);
    #pragma unroll
    for (int i = 0; i < 8; i++) {
        float4 o;
        o.x = acc[i][0].x + bo.x; o.y = acc[i][0].y + bo.y;
        o.z = acc[i][1].x + bo.z; o.w = acc[i][1].y + bo.w;
        *(float4*)(out + (size_t)(b0 + m0 + i) * V + n) = o;
    }
}

// ---------------------------------------------------------------------------
extern "C" void kernel_launch(void* const* d_in, const int* in_sizes, int n_in,
                              void* d_out, int out_size)
{
    const int*   seq   = (const int*)  d_in[0];
    const float* embed = (const float*)d_in[1];
    const float* W1    = (const float*)d_in[2];
    const float* b1    = (const float*)d_in[3];
    const float* W2    = (const float*)d_in[4];
    const float* b2    = (const float*)d_in[5];
    const float* gamma = (const float*)d_in[6];
    const float* beta  = (const float*)d_in[7];
    const float* Wrp   = (const float*)d_in[8];
    const float* brp   = (const float*)d_in[9];
    const float* Wout  = (const float*)d_in[10];
    const float* bout  = (const float*)d_in[11];
    float* out = (float*)d_out;

    cudaFuncSetAttribute(encode_mma_kernel,
                         cudaFuncAttributeMaxDynamicSharedMemorySize, ENC_SMEM);

    prep_kernel<<<256, 256>>>(W1, W2);
    encode_mma_kernel<<<BL / TOK, 256, ENC_SMEM>>>(seq, embed, b1, b2, gamma, beta);
    scan_kernel<<<B, 128>>>();
    rp_kernel<<<B, H>>>(Wrp, brp);
    dim3 og(V / 128, B / 64);
    out_kernel<<<og, 256>>>(Wout, bout, out);
}

// round 10
// speedup vs baseline: 1.3360x; 1.0200x over previous
#include <cuda_runtime.h>
#include <cuda_bf16.h>
#include <cstdint>
#include <cstddef>

#define B 256
#define L 2048
#define H 128
#define V 32000
#define BL (B * L)
#define TOK 128

typedef unsigned long long u64;
typedef uint32_t u32;

// ---------------------------------------------------------------------------
// helpers
// ---------------------------------------------------------------------------
__device__ __forceinline__ u32 smem_u32(const void* p) {
    return (u32)__cvta_generic_to_shared(p);
}

__device__ __forceinline__ void ldsm_x4(u32* r, u32 addr) {
    asm volatile("ldmatrix.sync.aligned.m8n8.x4.shared.b16 {%0,%1,%2,%3}, [%4];"
                 : "=r"(r[0]), "=r"(r[1]), "=r"(r[2]), "=r"(r[3]) : "r"(addr));
}

__device__ __forceinline__ void mma16816(float* d, const u32* a, u32 b0, u32 b1) {
    asm volatile(
        "mma.sync.aligned.m16n8k16.row.col.f32.bf16.bf16.f32 "
        "{%0,%1,%2,%3}, {%4,%5,%6,%7}, {%8,%9}, {%0,%1,%2,%3};"
        : "+f"(d[0]), "+f"(d[1]), "+f"(d[2]), "+f"(d[3])
        : "r"(a[0]), "r"(a[1]), "r"(a[2]), "r"(a[3]), "r"(b0), "r"(b1));
}

__device__ __forceinline__ void cp16(u32 dst, const void* src) {
    asm volatile("cp.async.cg.shared.global [%0], [%1], 16;" :: "r"(dst), "l"(src));
}

// Packed dual-FMA (scan/out kernels).
__device__ __forceinline__ float2 ffma2(float2 a, float2 b, float2 c) {
    float2 d;
    asm("fma.rn.f32x2 %0, %1, %2, %3;"
        : "=l"(*(u64*)&d)
        : "l"(*(u64*)&a), "l"(*(u64*)&b), "l"(*(u64*)&c));
    return d;
}

// 3-way bf16 split: x = a0+a1+a2 + O(2^-27 * x)
__device__ __forceinline__ void split3(float x, __nv_bfloat16* a) {
    a[0] = __float2bfloat16(x);
    float r = x - __bfloat162float(a[0]);
    a[1] = __float2bfloat16(r);  r -= __bfloat162float(a[1]);
    a[2] = __float2bfloat16(r);
}
__device__ __forceinline__ u32 pack_bf2(__nv_bfloat16 lo, __nv_bfloat16 hi) {
    __nv_bfloat162 p;
    p.x = lo; p.y = hi;
    return *(u32*)&p;
}

// XOR chunk swizzles: conflict-free ldmatrix on natural row strides.
__device__ __forceinline__ u32 swz256(int row, int kb) {
    return (u32)(row * 256 + ((((kb >> 4) ^ (row & 7)) << 4) | (kb & 15)));
}
__device__ __forceinline__ u32 swz128(int row, int kb) {
    return (u32)(row * 128 + ((((kb >> 4) ^ (row & 7)) << 4) | (kb & 15)));
}

// ---------------------------------------------------------------------------
// Scratch device globals.
// ---------------------------------------------------------------------------
__device__ float g_h[(size_t)BL * H];
__device__ float g_r[B * H];
__device__ float g_rp[B * H];
// Pre-split, pre-swizzled weight part-tiles (3 parts):
// g_W1s: [c=4][p=3][16384]  tile = 64 n-rows x 128 k bf16, swz256 rows
// g_W2s: [c=4][p=3][16384]  tile = 128 n-rows x 64 k bf16, swz128 rows
__device__ unsigned char g_W1s[4 * 3 * 16384];
__device__ unsigned char g_W2s[4 * 3 * 16384];

// ---------------------------------------------------------------------------
// Prep: split3 + transpose + swizzle the weights.
// ---------------------------------------------------------------------------
__global__ void __launch_bounds__(256) prep_kernel(
    const float* __restrict__ W1, const float* __restrict__ W2)
{
    int idx = blockIdx.x * 256 + threadIdx.x;   // 65536 total
    __nv_bfloat16 pp[3];
    if (idx < H * 2 * H) {                      // W1: [k=128][n=256]
        int k = idx >> 8;
        int n = idx & 255;
        split3(W1[idx], pp);
        int c = n >> 6, nl = n & 63;
        u32 off = swz256(nl, 2 * k);
        unsigned char* base = g_W1s + (size_t)c * 49152 + off;
        #pragma unroll
        for (int p = 0; p < 3; p++)
            *(__nv_bfloat16*)(base + p * 16384) = pp[p];
    } else {                                    // W2: [k2=256][n=128]
        int j  = idx - H * 2 * H;
        int k2 = j >> 7;
        int n  = j & 127;
        split3(W2[j], pp);
        int c = k2 >> 6, kl = k2 & 63;
        u32 off = swz128(n, 2 * kl);
        unsigned char* base = g_W2s + (size_t)c * 49152 + off;
        #pragma unroll
        for (int p = 0; p < 3; p++)
            *(__nv_bfloat16*)(base + p * 16384) = pp[p];
    }
}

// Stage schedule: s = c*6 + g*3 + jj, W part j = 2-jj (smallest products first).
__device__ __forceinline__ const unsigned char* stage_src(int s) {
    int c = s / 6, g = (s / 3) % 2, jj = s % 3;
    int j = 2 - jj;
    return (g ? g_W2s : g_W1s) + (size_t)c * 49152 + (size_t)j * 16384;
}

// ---------------------------------------------------------------------------
// Encode via bf16 mma.sync, 3-way split (6 products). Identical math order to
// R9 (W parts j=2,1,0; A parts i descending; k16 descending) but with
// (a) triple-buffered W stream -> single __syncthreads per stage,
// (b) software-pipelined ldmatrix (double-buffered fragment registers).
// 256 threads, 128 tokens per CTA, grid 4096, 1 CTA/SM.
// SMEM (199168 B): E 3x32768 @0 | A2 3x16384 @98304 | W 3x16384 @147456
//                  consts @196608 (b1 256f, b2/g/b 128f each)
// ---------------------------------------------------------------------------
#define EO       0
#define EPART    32768
#define A2O      98304
#define A2PART   16384
#define WO       147456
#define CO       196608
#define ENC_SMEM 199168

__global__ void __launch_bounds__(256, 1) encode_mma_kernel(
    const int* __restrict__ seq, const float* __restrict__ embed,
    const float* __restrict__ b1, const float* __restrict__ b2,
    const float* __restrict__ gamma, const float* __restrict__ beta)
{
    extern __shared__ char smc[];
    const u32 sb = smem_u32(smc);
    float* b1s = (float*)(smc + CO);
    float* b2s = b1s + 256;
    float* gs  = b2s + 128;
    float* bs  = gs + 128;

    const int t    = threadIdx.x;
    const int lane = t & 31;
    const int w    = t >> 5;
    const int tile0 = blockIdx.x * TOK;

    // Kick off first weight-part load immediately (overlaps E gather).
    {
        const unsigned char* src = stage_src(0) + t * 64;
        u32 dst = sb + WO + t * 64;
        cp16(dst, src); cp16(dst + 16, src + 16);
        cp16(dst + 32, src + 32); cp16(dst + 48, src + 48);
        asm volatile("cp.async.commit_group;");
    }

    b1s[t] = b1[t];
    if (t < 128) { b2s[t] = b2[t]; gs[t] = gamma[t]; bs[t] = beta[t]; }

    // ---- gather + split3 E: two threads per token ----
    {
        int row = t >> 1, kh = t & 1;
        int tok = seq[tile0 + row];
        const float4* er = (const float4*)(embed + (size_t)tok * H) + kh * 16;
        #pragma unroll 4
        for (int i = 0; i < 16; i++) {
            float4 v = er[i];
            int col0 = kh * 64 + 4 * i;
            u32 offA = swz256(row, 2 * col0);
            __nv_bfloat16 px[3], py[3];
            split3(v.x, px); split3(v.y, py);
            #pragma unroll
            for (int p = 0; p < 3; p++)
                *(u32*)(smc + EO + p * EPART + offA) = pack_bf2(px[p], py[p]);
            split3(v.z, px); split3(v.w, py);
            #pragma unroll
            for (int p = 0; p < 3; p++)
                *(u32*)(smc + EO + p * EPART + offA + 4) = pack_bf2(px[p], py[p]);
        }
    }

    const int m0   = (w >> 1) * 32;
    const int n0g1 = (w & 1) * 32;
    const int n0g2 = (w & 1) * 64;
    const int lg   = lane >> 3;
    const int rsel = (lane & 7) + ((lg & 1) << 3);
    const int kbs  = (lg >> 1) << 4;
    const int frow = lane >> 2;
    const int fcol = 2 * (lane & 3);

    float c1[2][4][4];
    float c2[2][8][4];
    #pragma unroll
    for (int mt = 0; mt < 2; mt++)
        #pragma unroll
        for (int nt = 0; nt < 8; nt++)
            #pragma unroll
            for (int jj = 0; jj < 4; jj++) c2[mt][nt][jj] = 0.f;

    // ---- 24 stages: chunk c x {GEMM1 parts j=2,1,0 ; GEMM2 parts j=2,1,0} ----
    for (int s = 0; s < 24; s++) {
        const int jj  = s % 3;       // stream index
        const int j   = 2 - jj;      // W part (2 first, 0 = dominant last)
        const int g   = (s / 3) % 2;
        const int buf = s % 3;

        // Prefetch next stage's W part into the third buffer (no conflict with
        // stage s-1 laggards reading buf (s-1)%3 or stage s reading buf s%3).
        if (s < 23) {
            const unsigned char* src = stage_src(s + 1) + t * 64;
            u32 dst = sb + WO + ((s + 1) % 3) * 16384 + t * 64;
            cp16(dst, src); cp16(dst + 16, src + 16);
            cp16(dst + 32, src + 32); cp16(dst + 48, src + 48);
            asm volatile("cp.async.commit_group;");
            asm volatile("cp.async.wait_group 1;");
        } else {
            asm volatile("cp.async.wait_group 0;");
        }
        __syncthreads();   // stage-s weight part visible; prev compute drained

        const u32 Bb = sb + WO + buf * 16384;

        if (g == 0) {
            // ---------------- GEMM1: C1 += E_i @ W1c_j^T ----------------
            if (jj == 0) {
                #pragma unroll
                for (int mt = 0; mt < 2; mt++)
                    #pragma unroll
                    for (int nt = 0; nt < 4; nt++)
                        #pragma unroll
                        for (int q = 0; q < 4; q++) c1[mt][nt][q] = 0.f;
            }
            for (int i = 2 - j; i >= 0; i--) {          // small first, a0 last
                const u32 Ab = sb + EO + i * EPART;
                u32 af[2][2][4], qf[2][2][4];           // [pipe buf][frag][4]
                {   // preload k16 = 7
                    const int kb = 7 * 32 + kbs;
                    ldsm_x4(af[0][0], Ab + swz256(m0 + rsel, kb));
                    ldsm_x4(af[0][1], Ab + swz256(m0 + 16 + rsel, kb));
                    ldsm_x4(qf[0][0], Bb + swz256(n0g1 + rsel, kb));
                    ldsm_x4(qf[0][1], Bb + swz256(n0g1 + 16 + rsel, kb));
                }
                #pragma unroll
                for (int k16 = 7; k16 >= 0; k16--) {    // reversed k-chunks
                    const int cur = (7 - k16) & 1;
                    if (k16 > 0) {                      // prefetch next frags
                        const int kb2 = (k16 - 1) * 32 + kbs;
                        ldsm_x4(af[cur ^ 1][0], Ab + swz256(m0 + rsel, kb2));
                        ldsm_x4(af[cur ^ 1][1], Ab + swz256(m0 + 16 + rsel, kb2));
                        ldsm_x4(qf[cur ^ 1][0], Bb + swz256(n0g1 + rsel, kb2));
                        ldsm_x4(qf[cur ^ 1][1], Bb + swz256(n0g1 + 16 + rsel, kb2));
                    }
                    #pragma unroll
                    for (int mt = 0; mt < 2; mt++)
                        #pragma unroll
                        for (int nt = 0; nt < 4; nt++)
                            mma16816(c1[mt][nt], af[cur][mt],
                                     qf[cur][nt >> 1][nt & 1],
                                     qf[cur][nt >> 1][2 + (nt & 1)]);
                }
            }
            if (jj == 2) {
                // ---- bias + relu + split3 -> A2 parts ----
                const int c = s / 6;
                #pragma unroll
                for (int mt = 0; mt < 2; mt++) {
                    #pragma unroll
                    for (int nt = 0; nt < 4; nt++) {
                        int col = n0g1 + nt * 8 + fcol;
                        float bb0 = b1s[c * 64 + col];
                        float bb1 = b1s[c * 64 + col + 1];
                        #pragma unroll
                        for (int half = 0; half < 2; half++) {
                            int row = m0 + mt * 16 + frow + half * 8;
                            float h0 = fmaxf(c1[mt][nt][2 * half + 0] + bb0, 0.f);
                            float h1 = fmaxf(c1[mt][nt][2 * half + 1] + bb1, 0.f);
                            __nv_bfloat16 px[3], py[3];
                            split3(h0, px); split3(h1, py);
                            u32 off = swz128(row, 2 * col);
                            #pragma unroll
                            for (int p = 0; p < 3; p++)
                                *(u32*)(smc + A2O + p * A2PART + off) =
                                    pack_bf2(px[p], py[p]);
                        }
                    }
                }
            }
        } else {
            // ---------------- GEMM2: C2 += A2_i @ W2c_j^T ----------------
            for (int i = 2 - j; i >= 0; i--) {
                const u32 Ab = sb + A2O + i * A2PART;
                u32 af[2][2][4], qf[2][4][4];
                {   // preload k16 = 3
                    const int kb = 3 * 32 + kbs;
                    ldsm_x4(af[0][0], Ab + swz128(m0 + rsel, kb));
                    ldsm_x4(af[0][1], Ab + swz128(m0 + 16 + rsel, kb));
                    #pragma unroll
                    for (int nt2 = 0; nt2 < 4; nt2++)
                        ldsm_x4(qf[0][nt2], Bb + swz128(n0g2 + nt2 * 16 + rsel, kb));
                }
                #pragma unroll
                for (int k16 = 3; k16 >= 0; k16--) {
                    const int cur = (3 - k16) & 1;
                    if (k16 > 0) {
                        const int kb2 = (k16 - 1) * 32 + kbs;
                        ldsm_x4(af[cur ^ 1][0], Ab + swz128(m0 + rsel, kb2));
                        ldsm_x4(af[cur ^ 1][1], Ab + swz128(m0 + 16 + rsel, kb2));
                        #pragma unroll
                        for (int nt2 = 0; nt2 < 4; nt2++)
                            ldsm_x4(qf[cur ^ 1][nt2],
                                    Bb + swz128(n0g2 + nt2 * 16 + rsel, kb2));
                    }
                    #pragma unroll
                    for (int mt = 0; mt < 2; mt++)
                        #pragma unroll
                        for (int nt = 0; nt < 8; nt++)
                            mma16816(c2[mt][nt], af[cur][mt],
                                     qf[cur][nt >> 1][nt & 1],
                                     qf[cur][nt >> 1][2 + (nt & 1)]);
                }
            }
        }
    }

    // ---- epilogue: y = ff + b2 + e (e from 3 SMEM parts) ----
    #pragma unroll
    for (int mt = 0; mt < 2; mt++) {
        #pragma unroll
        for (int nt = 0; nt < 8; nt++) {
            int col = n0g2 + nt * 8 + fcol;
            float bb0 = b2s[col], bb1 = b2s[col + 1];
            #pragma unroll
            for (int half = 0; half < 2; half++) {
                int row = m0 + mt * 16 + frow + half * 8;
                u32 off = swz256(row, 2 * col);
                float e0 = 0.f, e1 = 0.f;
                #pragma unroll
                for (int p = 2; p >= 0; p--) {
                    u32 ev = *(u32*)(smc + EO + p * EPART + off);
                    __nv_bfloat162 eb = *(__nv_bfloat162*)&ev;
                    e0 += __bfloat162float(eb.x);
                    e1 += __bfloat162float(eb.y);
                }
                c2[mt][nt][2 * half + 0] += bb0 + e0;
                c2[mt][nt][2 * half + 1] += bb1 + e1;
            }
        }
    }
    __syncthreads();   // all E reads done before overwrite

    // ---- y -> ySM (stride 132 floats, reuses E region), LN, write g_h ----
    float* ySM = (float*)(smc + EO);
    float* muS = (float*)(smc + A2O);
    float* ivS = muS + 128;
    #pragma unroll
    for (int mt = 0; mt < 2; mt++) {
        #pragma unroll
        for (int nt = 0; nt < 8; nt++) {
            int col = n0g2 + nt * 8 + fcol;
            #pragma unroll
            for (int half = 0; half < 2; half++) {
                int row = m0 + mt * 16 + frow + half * 8;
                *(float2*)(ySM + row * 132 + col) =
                    make_float2(c2[mt][nt][2 * half + 0], c2[mt][nt][2 * half + 1]);
            }
        }
    }
    __syncthreads();

    if (t < 128) {
        const float4* yr = (const float4*)(ySM + t * 132);
        float s = 0.f, q = 0.f;
        #pragma unroll 8
        for (int jj = 0; jj < 32; jj++) {
            float4 y = yr[jj];
            s += (y.x + y.y) + (y.z + y.w);
            q += y.x * y.x + y.y * y.y + y.z * y.z + y.w * y.w;
        }
        float mu  = s * (1.0f / H);
        float var = q * (1.0f / H) - mu * mu;
        muS[t] = mu;
        ivS[t] = rsqrtf(var + 1e-5f);
    }
    __syncthreads();

    #pragma unroll
    for (int i = t; i < 128 * 32; i += 256) {
        int row = i >> 5, jj = i & 31;
        float4 y = ((const float4*)(ySM + row * 132))[jj];
        float mu = muS[row], iv = ivS[row];
        float4 g4 = ((const float4*)gs)[jj];
        float4 b4 = ((const float4*)bs)[jj];
        float4 o4;
        o4.x = (y.x - mu) * iv * g4.x + b4.x;
        o4.y = (y.y - mu) * iv * g4.y + b4.y;
        o4.z = (y.z - mu) * iv * g4.z + b4.z;
        o4.w = (y.w - mu) * iv * g4.w + b4.w;
        ((float4*)(g_h + (size_t)(tile0 + row) * H))[jj] = o4;
    }
}

// ---------------------------------------------------------------------------
// Scan: one CTA per batch (unchanged from R5/R9).
// ---------------------------------------------------------------------------
__global__ void __launch_bounds__(128, 2) scan_kernel()
{
    const int b = blockIdx.x;
    const int tid = threadIdx.x;
    const int lane = tid & 31;
    const int wid = tid >> 5;

    __shared__ float ks[2][H];
    __shared__ float red_kk[4];
    __shared__ float red_ee[4];

    float2 Mr[64];
    #pragma unroll
    for (int q = 0; q < 64; q++) Mr[q] = make_float2(0.f, 0.f);

    const float* hb = g_h + (size_t)b * L * H;
    float kv_next = hb[tid];

    for (int t = 0; t < L - 1; t++) {
        const int buf = t & 1;
        const float kv = kv_next;
        ks[buf][tid] = kv;

        float p = kv * kv;
        #pragma unroll
        for (int o = 16; o; o >>= 1) p += __shfl_xor_sync(0xffffffffu, p, o);
        if (lane == 0) red_kk[wid] = p;
        __syncthreads();

        kv_next = hb[(size_t)(t + 1) * H + tid];
        const float kk = (red_kk[0] + red_kk[1]) + (red_kk[2] + red_kk[3]);

        const float4* k4 = (const float4*)ks[buf];
        float2 a0 = make_float2(0.f, 0.f), a1 = a0, a2 = a0, a3 = a0;
        #pragma unroll
        for (int q = 0; q < 32; q += 2) {
            float4 ka = k4[q];
            float4 kb = k4[q + 1];
            const float2* kap = reinterpret_cast<const float2*>(&ka);
            const float2* kbp = reinterpret_cast<const float2*>(&kb);
            a0 = ffma2(Mr[2 * q + 0], kap[0], a0);
            a1 = ffma2(Mr[2 * q + 1], kap[1], a1);
            a2 = ffma2(Mr[2 * q + 2], kbp[0], a2);
            a3 = ffma2(Mr[2 * q + 3], kbp[1], a3);
        }
        const float vp = ((a0.x + a0.y) + (a1.x + a1.y))
                       + ((a2.x + a2.y) + (a3.x + a3.y));
        const float err = kv - vp / (kk + 1e-6f);

        float pe = err * err;
        #pragma unroll
        for (int o = 16; o; o >>= 1) pe += __shfl_xor_sync(0xffffffffu, pe, o);
        if (lane == 0) red_ee[wid] = pe;
        __syncthreads();
        const float ee = (red_ee[0] + red_ee[1]) + (red_ee[2] + red_ee[3]);

        if (ee > 0.16f * kk) {
            const float2 e2 = make_float2(err, err);
            #pragma unroll
            for (int q = 0; q < 32; q++) {
                float4 kq = k4[q];
                const float2* kp = reinterpret_cast<const float2*>(&kq);
                Mr[2 * q + 0] = ffma2(e2, kp[0], Mr[2 * q + 0]);
                Mr[2 * q + 1] = ffma2(e2, kp[1], Mr[2 * q + 1]);
            }
        }
    }

    ks[1][tid] = kv_next;
    __syncthreads();
    const float4* k4 = (const float4*)ks[1];
    float2 a0 = make_float2(0.f, 0.f), a1 = a0, a2 = a0, a3 = a0;
    #pragma unroll
    for (int q = 0; q < 32; q += 2) {
        float4 ka = k4[q];
        float4 kb = k4[q + 1];
        const float2* kap = reinterpret_cast<const float2*>(&ka);
        const float2* kbp = reinterpret_cast<const float2*>(&kb);
        a0 = ffma2(Mr[2 * q + 0], kap[0], a0);
        a1 = ffma2(Mr[2 * q + 1], kap[1], a1);
        a2 = ffma2(Mr[2 * q + 2], kbp[0], a2);
        a3 = ffma2(Mr[2 * q + 3], kbp[1], a3);
    }
    g_r[b * H + tid] = ((a0.x + a0.y) + (a1.x + a1.y))
                     + ((a2.x + a2.y) + (a3.x + a3.y));
}

// ---------------------------------------------------------------------------
__global__ void rp_kernel(const float* __restrict__ Wrp, const float* __restrict__ brp)
{
    const int b = blockIdx.x;
    const int i = threadIdx.x;
    __shared__ float rb[H];
    rb[i] = g_r[b * H + i];
    __syncthreads();
    float acc = brp[i];
    #pragma unroll 8
    for (int j = 0; j < H; j++) acc += rb[j] * Wrp[j * H + i];
    g_rp[b * H + i] = acc;
}

// ---------------------------------------------------------------------------
__global__ void __launch_bounds__(256) out_kernel(
    const float* __restrict__ Wout, const float* __restrict__ bout,
    float* __restrict__ out)
{
    __shared__ float rp_sm[64 * H];
    const int t = threadIdx.x;
    const int v0 = blockIdx.x * 128;
    const int b0 = blockIdx.y * 64;

    #pragma unroll
    for (int i = 0; i < 32; i++) {
        int idx = i * 256 + t;
        rp_sm[idx] = g_rp[b0 * H + idx];
    }
    __syncthreads();

    const int tx = t & 31;
    const int ty = t >> 5;
    const int m0 = ty * 8;
    const int n  = v0 + tx * 4;

    float2 acc[8][2];
    #pragma unroll
    for (int i = 0; i < 8; i++) {
        acc[i][0] = make_float2(0.f, 0.f);
        acc[i][1] = make_float2(0.f, 0.f);
    }

    #pragma unroll 2
    for (int k = 0; k < H; k++) {
        float4 wv = *(const float4*)(Wout + (size_t)k * V + n);
        const float2* wp = reinterpret_cast<const float2*>(&wv);
        #pragma unroll
        for (int i = 0; i < 8; i++) {
            float hv = rp_sm[(m0 + i) * H + k];
            float2 h2 = make_float2(hv, hv);
            acc[i][0] = ffma2(h2, wp[0], acc[i][0]);
            acc[i][1] = ffma2(h2, wp[1], acc[i][1]);
        }
    }
    const float4 bo = *(const float4*)(bout + n);
    #pragma unroll
    for (int i = 0; i < 8; i++) {
        float4 o;
        o.x = acc[i][0].x + bo.x; o.y = acc[i][0].y + bo.y;
        o.z = acc[i][1].x + bo.z; o.w = acc[i][1].y + bo.w;
        *(float4*)(out + (size_t)(b0 + m0 + i) * V + n) = o;
    }
}

// ---------------------------------------------------------------------------
extern "C" void kernel_launch(void* const* d_in, const int* in_sizes, int n_in,
                              void* d_out, int out_size)
{
    const int*   seq   = (const int*)  d_in[0];
    const float* embed = (const float*)d_in[1];
    const float* W1    = (const float*)d_in[2];
    const float* b1    = (const float*)d_in[3];
    const float* W2    = (const float*)d_in[4];
    const float* b2    = (const float*)d_in[5];
    const float* gamma = (const float*)d_in[6];
    const float* beta  = (const float*)d_in[7];
    const float* Wrp   = (const float*)d_in[8];
    const float* brp   = (const float*)d_in[9];
    const float* Wout  = (const float*)d_in[10];
    const float* bout  = (const float*)d_in[11];
    float* out = (float*)d_out;

    cudaFuncSetAttribute(encode_mma_kernel,
                         cudaFuncAttributeMaxDynamicSharedMemorySize, ENC_SMEM);

    prep_kernel<<<256, 256>>>(W1, W2);
    encode_mma_kernel<<<BL / TOK, 256, ENC_SMEM>>>(seq, embed, b1, b2, gamma, beta);
    scan_kernel<<<B, 128>>>();
    rp_kernel<<<B, H>>>(Wrp, brp);
    dim3 og(V / 128, B / 64);
    out_kernel<<<og, 256>>>(Wout, bout, out);
}